// round 4
// baseline (speedup 1.0000x reference)
#include <cuda_runtime.h>
#include <cuda_bf16.h>
#include <cstdint>

// Problem constants
#define B_      8
#define S_      512
#define E_      128
#define D_      512
#define VOCAB_  32000
#define LN_EPS  1e-5f

// Scratch for m[b][o][i]  (8*512*128 floats = 2MB) — static __device__ (no allocs)
__device__ float g_m[B_ * D_ * E_];

// Packed f32x2 FMA (Blackwell sm_10x): d = a*b + c on both 32-bit halves.
__device__ __forceinline__ unsigned long long ffma2(
    unsigned long long a, unsigned long long b, unsigned long long c)
{
    unsigned long long d;
    asm("fma.rn.f32x2 %0, %1, %2, %3;" : "=l"(d) : "l"(a), "l"(b), "l"(c));
    return d;
}

__device__ __forceinline__ float fold2(unsigned long long v)
{
    const float lo = __int_as_float((int)(unsigned)(v & 0xffffffffULL));
    const float hi = __int_as_float((int)(unsigned)(v >> 32));
    return lo + hi;
}

// ---------------------------------------------------------------------------
// Kernel A: m[b,o,i] = sum_j W[o,i,j] * king_emb_table[king_id[b], j]
// One block per o (512 blocks), 128 threads (4 warps). HBM-bound (33.5 MB W).
// Lane owns j-slice [4*lane, 4*lane+3]; the 8 king float4s for that slice are
// loop-invariant -> held in registers. Per i-row: ONE coalesced LDG.128 per
// lane (512B/warp), 32 FMAs, 9-shuffle halving butterfly reducing all 8 batch
// dots at once. Result staged in smem, flushed coalesced.
// ---------------------------------------------------------------------------
__global__ __launch_bounds__(128, 8) void compute_m_kernel(
    const float* __restrict__ W,
    const float* __restrict__ king_tab,
    const int*   __restrict__ king_id)
{
    const int o    = blockIdx.x;
    const int t    = threadIdx.x;
    const int lane = t & 31;
    const int w    = t >> 5;     // warp 0..3

    __shared__ float king_s[8][E_];   // 4 KB
    __shared__ float m_s[8][132];     // padded

    // Cooperative load of the 8 selected king rows (8*128 = 1024 floats)
    for (int r = t; r < 8 * (E_ / 4); r += 128) {
        const int b  = r >> 5;            // 32 float4 per row
        const int i4 = r & 31;
        const int kid = king_id[b];
        ((float4*)king_s[b])[i4] =
            ((const float4*)(king_tab + (size_t)kid * E_))[i4];
    }
    __syncthreads();

    // Loop-invariant king values for my j-slice (j = 4*lane .. 4*lane+3)
    float4 kv[8];
    #pragma unroll
    for (int b = 0; b < 8; b++)
        kv[b] = ((const float4*)king_s[b])[lane];

    const float4* Wo = (const float4*)(W + (size_t)o * E_ * E_);

    #pragma unroll 4
    for (int i = w; i < E_; i += 4) {
        const float4 wv = Wo[i * (E_ / 4) + lane];   // coalesced 512B/warp

        float acc[8];
        #pragma unroll
        for (int b = 0; b < 8; b++) {
            acc[b]  = wv.x * kv[b].x;
            acc[b] += wv.y * kv[b].y;
            acc[b] += wv.z * kv[b].z;
            acc[b] += wv.w * kv[b].w;
        }

        // Halving butterfly: 8 values over 32 lanes -> 9 shuffles total.
        // Stage xor16: 8 -> 4 values
        #pragma unroll
        for (int x = 0; x < 4; x++) {
            const float lo = acc[x], hi = acc[x + 4];
            const float sel = (lane & 16) ? lo : hi;
            const float got = __shfl_xor_sync(0xffffffffu, sel, 16);
            acc[x] = ((lane & 16) ? hi : lo) + got;
        }
        // Stage xor8: 4 -> 2
        #pragma unroll
        for (int x = 0; x < 2; x++) {
            const float lo = acc[x], hi = acc[x + 2];
            const float sel = (lane & 8) ? lo : hi;
            const float got = __shfl_xor_sync(0xffffffffu, sel, 8);
            acc[x] = ((lane & 8) ? hi : lo) + got;
        }
        // Stage xor4: 2 -> 1
        {
            const float lo = acc[0], hi = acc[1];
            const float sel = (lane & 4) ? lo : hi;
            const float got = __shfl_xor_sync(0xffffffffu, sel, 4);
            acc[0] = ((lane & 4) ? hi : lo) + got;
        }
        // Finish sum over the 4 lanes sharing the same b
        acc[0] += __shfl_xor_sync(0xffffffffu, acc[0], 2);
        acc[0] += __shfl_xor_sync(0xffffffffu, acc[0], 1);

        // b = bits {4,3,2} of lane; lanes with (lane&3)==0 write
        if ((lane & 3) == 0) m_s[(lane >> 2)][i] = acc[0];
    }
    __syncthreads();

    // Coalesced flush: m[bb][o][t]
    #pragma unroll
    for (int bb = 0; bb < 8; bb++)
        g_m[(size_t)bb * D_ * E_ + (size_t)o * E_ + t] = m_s[bb][t];
}

// ---------------------------------------------------------------------------
// Kernel B: fused gather + GEMM + bias + LayerNorm, packed-f32x2 mainloop.
// Block = (b, 16-row s-tile) -> 256 blocks, 256 threads, target 2 blocks/SM.
// Thread (sg = t>>6 in 0..3, og = t&63): 4s x 8o register tile,
//   s = sg*4 + ss, o = og + 64*oo (coalesced stores).
// Single m base pointer; per-oo offsets are compile-time immediates.
// ---------------------------------------------------------------------------
#define ST_ 16

__global__ __launch_bounds__(256, 2) void gemm_ln_kernel(
    const int*   __restrict__ seq,
    const int*   __restrict__ king_id,
    const float* __restrict__ emb,
    const float* __restrict__ bias,
    const float* __restrict__ gamma,
    const float* __restrict__ beta,
    float*       __restrict__ out)
{
    const int blk = blockIdx.x;          // 0..255
    const int b   = blk >> 5;            // 32 s-tiles per batch
    const int s0  = (blk & 31) * ST_;
    const int t   = threadIdx.x;
    const int og  = t & 63;
    const int sg  = t >> 6;              // 0..3

    __shared__ float A_s[ST_][E_];        // 8 KB
    __shared__ float red[2][ST_][66];     // padded
    __shared__ float mu_s[ST_], rs_s[ST_];

    // --- Gather embedding rows (coalesced float4 per row)
    {
        const int kid = king_id[b];
        const float* etab = emb + (size_t)kid * VOCAB_ * E_;
        #pragma unroll
        for (int r = t; r < ST_ * (E_ / 4); r += 256) {
            const int s  = r >> 5;        // 32 float4 per row
            const int i4 = r & 31;
            const int tok = seq[b * S_ + s0 + s];
            ((float4*)A_s[s])[i4] = ((const float4*)(etab + (size_t)tok * E_))[i4];
        }
    }
    __syncthreads();

    // Single base pointer for m; o = og + 64*oo -> immediate offset oo*2048 (ull2)
    const ulonglong2* Mrow =
        (const ulonglong2*)(g_m + (size_t)b * D_ * E_ + (size_t)og * E_);

    unsigned long long acc2[4][8];
    #pragma unroll
    for (int ss = 0; ss < 4; ss++)
        #pragma unroll
        for (int oo = 0; oo < 8; oo++)
            acc2[ss][oo] = 0ULL;

    // --- K loop: 32 steps of 4 k-elements (2 packed pairs)
    #pragma unroll 2
    for (int i4 = 0; i4 < E_ / 4; i4++) {
        ulonglong2 a2[4];
        #pragma unroll
        for (int ss = 0; ss < 4; ss++)
            a2[ss] = ((const ulonglong2*)A_s[sg * 4 + ss])[i4];  // warp broadcast
        #pragma unroll
        for (int oo = 0; oo < 8; oo++) {
            const ulonglong2 mv = Mrow[i4 + oo * 2048];   // imm offset, 1 ptr reg
            #pragma unroll
            for (int ss = 0; ss < 4; ss++) {
                acc2[ss][oo] = ffma2(a2[ss].x, mv.x, acc2[ss][oo]);
                acc2[ss][oo] = ffma2(a2[ss].y, mv.y, acc2[ss][oo]);
            }
        }
    }

    // --- fold packed halves + bias
    float accf[4][8];
    #pragma unroll
    for (int oo = 0; oo < 8; oo++) {
        const float bo = bias[og + 64 * oo];
        #pragma unroll
        for (int ss = 0; ss < 4; ss++)
            accf[ss][oo] = fold2(acc2[ss][oo]) + bo;
    }

    // --- LN phase 1: per-thread partials over its 8 o's
    #pragma unroll
    for (int ss = 0; ss < 4; ss++) {
        float ls = 0.f, lq = 0.f;
        #pragma unroll
        for (int oo = 0; oo < 8; oo++) {
            const float v = accf[ss][oo];
            ls += v;
            lq += v * v;
        }
        red[0][sg * 4 + ss][og] = ls;
        red[1][sg * 4 + ss][og] = lq;
    }
    __syncthreads();

    // --- LN phase 2: 8 threads per s reduce 64 partials (t < 128)
    if (t < 128) {
        const int s = t >> 3;     // 0..15
        const int k = t & 7;
        float ps = 0.f, pq = 0.f;
        #pragma unroll
        for (int j = 0; j < 8; j++) {
            ps += red[0][s][k + 8 * j];
            pq += red[1][s][k + 8 * j];
        }
        #pragma unroll
        for (int d = 1; d < 8; d <<= 1) {
            ps += __shfl_xor_sync(0xffffffffu, ps, d);
            pq += __shfl_xor_sync(0xffffffffu, pq, d);
        }
        if (k == 0) {
            const float mean = ps * (1.f / (float)D_);
            const float var  = pq * (1.f / (float)D_) - mean * mean;
            mu_s[s] = mean;
            rs_s[s] = rsqrtf(var + LN_EPS);
        }
    }
    __syncthreads();

    // --- normalize + affine + coalesced store
    #pragma unroll
    for (int ss = 0; ss < 4; ss++) {
        const int s = sg * 4 + ss;
        const float mu = mu_s[s];
        const float rs = rs_s[s];
        float* orow = out + ((size_t)(b * S_ + s0 + s)) * D_;
        #pragma unroll
        for (int oo = 0; oo < 8; oo++) {
            const int o = og + 64 * oo;
            orow[o] = (accf[ss][oo] - mu) * rs * gamma[o] + beta[o];
        }
    }
}

// ---------------------------------------------------------------------------
extern "C" void kernel_launch(void* const* d_in, const int* in_sizes, int n_in,
                              void* d_out, int out_size)
{
    const int*   seq      = (const int*)  d_in[0];  // (8, 512) int32
    const int*   king_id  = (const int*)  d_in[1];  // (8,) int32
    const float* emb      = (const float*)d_in[2];  // (27, 32000, 128)
    const float* king_tab = (const float*)d_in[3];  // (27, 128)
    const float* W        = (const float*)d_in[4];  // (512, 128, 128)
    const float* bias     = (const float*)d_in[5];  // (512,)
    const float* gamma    = (const float*)d_in[6];  // (512,)
    const float* beta     = (const float*)d_in[7];  // (512,)
    float*       out      = (float*)d_out;          // (8, 512, 512)

    compute_m_kernel<<<D_, 128>>>(W, king_tab, king_id);
    gemm_ln_kernel<<<B_ * (S_ / ST_), 256>>>(seq, king_id, emb, bias, gamma, beta, out);
}